// round 3
// baseline (speedup 1.0000x reference)
#include <cuda_runtime.h>
#include <math.h>

#define NN 50000
#define EE 800000
#define ETOT (EE + NN)
#define GG 512
#define FULL 0xffffffffu

// ---------------- scratch (device globals: the sanctioned allocation-free path) ----
__device__ int   g_is64;
__device__ int   d_cnt[NN];
__device__ int   d_rowptr[NN + 1];
__device__ int   d_cursor[NN];
__device__ float d_dis[NN];
__device__ int   d_csrc[ETOT];
__device__ float d_h1s[NN * 64];     // (x@W1)*dis
__device__ float d_g1[NN * 64];      // relu(GCN out)
__device__ float d_h2[NN * 128];     // g1@W2
__device__ float2 d_als2[NN];
__device__ float2 d_ald2[NN];
__device__ float d_g2[NN * 128];     // relu(GAT2 out)
__device__ float d_h3[NN * 64];      // g2@W3
__device__ float d_als3[NN];
__device__ float d_ald3[NN];
__device__ float d_g3[NN * 64];      // GAT3 out
__device__ int   d_start[GG + 1];

// ---------------- helpers ----------------
__device__ __forceinline__ int ld_idx(const void* p, int i, int is64) {
    return is64 ? (int)((const long long*)p)[i] : ((const int*)p)[i];
}
__device__ __forceinline__ float leaky(float v) { return v > 0.f ? v : 0.2f * v; }

// ---------------- index-width detection ----------------
__global__ void detect_kernel(const void* ei) {
    const long long* p = (const long long*)ei;
    int ok = 1;
#pragma unroll
    for (int i = 0; i < 4; i++) {
        long long v = p[i];
        if (v < 0 || v >= NN) ok = 0;
    }
    g_is64 = ok;
}

// ---------------- CSR build ----------------
__global__ void init_kernel(int n) {
    int i = blockIdx.x * blockDim.x + threadIdx.x;
    if (i < n) d_cnt[i] = 1;            // self-loop
    if (i <= GG) d_start[i] = n;        // default boundary (empty graphs)
}

__global__ void count_kernel(const void* ei, int E) {
    int is64 = g_is64;
    int e = blockIdx.x * blockDim.x + threadIdx.x;
    if (e < E) {
        int d = ld_idx(ei, E + e, is64);
        atomicAdd(&d_cnt[d], 1);
    }
}

__global__ void scan_kernel(int n) {
    __shared__ int ssum[1024];
    int t = threadIdx.x;
    int chunk = (n + 1023) / 1024;
    int b = t * chunk;
    int e = min(b + chunk, n);
    int s = 0;
    for (int i = b; i < e; i++) s += d_cnt[i];
    ssum[t] = s;
    __syncthreads();
    for (int off = 1; off < 1024; off <<= 1) {
        int v = (t >= off) ? ssum[t - off] : 0;
        __syncthreads();
        ssum[t] += v;
        __syncthreads();
    }
    int p = ssum[t] - s;
    for (int i = b; i < e; i++) {
        int c = d_cnt[i];
        d_rowptr[i] = p;
        d_cursor[i] = p;
        d_dis[i] = rsqrtf((float)c);
        p += c;
    }
    if (t == 1023) d_rowptr[n] = ssum[1023];
}

__global__ void scatter_kernel(const void* ei, int E, int n) {
    int is64 = g_is64;
    int t = blockIdx.x * blockDim.x + threadIdx.x;
    if (t < E) {
        int s = ld_idx(ei, t, is64);
        int d = ld_idx(ei, E + t, is64);
        int pos = atomicAdd(&d_cursor[d], 1);
        d_csrc[pos] = s;
    } else if (t < E + n) {
        int i = t - E;
        int pos = atomicAdd(&d_cursor[i], 1);
        d_csrc[pos] = i;
    }
}

// ---------------- GEMM 1: h1s = (x @ W1) * dis,   x[N,128], W1[128,64] ----------------
__global__ void gemm1_kernel(const float* __restrict__ x, const float* __restrict__ W1, int n) {
    __shared__ float Wsm[128 * 64];
    for (int i = threadIdx.x; i < 128 * 64; i += blockDim.x) Wsm[i] = W1[i];
    __syncthreads();
    int warp = threadIdx.x >> 5, lane = threadIdx.x & 31;
    const float2* Wp = (const float2*)Wsm;
    for (int row = blockIdx.x * 8 + warp; row < n; row += gridDim.x * 8) {
        const float* xr = x + (size_t)row * 128;
        float a0 = 0.f, a1 = 0.f;
#pragma unroll
        for (int c = 0; c < 4; c++) {
            float xv = xr[c * 32 + lane];
#pragma unroll
            for (int kk = 0; kk < 32; kk++) {
                float xb = __shfl_sync(FULL, xv, kk);
                float2 w = Wp[(c * 32 + kk) * 32 + lane];
                a0 += xb * w.x;
                a1 += xb * w.y;
            }
        }
        float d = d_dis[row];
        ((float2*)d_h1s)[row * 32 + lane] = make_float2(a0 * d, a1 * d);
    }
}

// ---------------- GCN aggregation: g1 = relu(dis * sum_src h1s[src] + b1) ----------------
__global__ void gcn_agg_kernel(const float* __restrict__ b1, int n) {
    int warp = threadIdx.x >> 5, lane = threadIdx.x & 31;
    int node = blockIdx.x * 8 + warp;
    if (node >= n) return;
    int beg = d_rowptr[node], end = d_rowptr[node + 1];
    float a0 = 0.f, a1 = 0.f;
    const float2* H = (const float2*)d_h1s;
    for (int base = beg; base < end; base += 32) {
        int rem = end - base;
        int my = (lane < rem) ? d_csrc[base + lane] : 0;
        int cnt = rem < 32 ? rem : 32;
        for (int t = 0; t < cnt; t++) {
            int s = __shfl_sync(FULL, my, t);
            float2 v = H[s * 32 + lane];
            a0 += v.x;
            a1 += v.y;
        }
    }
    float d = d_dis[node];
    float2 bb = ((const float2*)b1)[lane];
    ((float2*)d_g1)[node * 32 + lane] =
        make_float2(fmaxf(a0 * d + bb.x, 0.f), fmaxf(a1 * d + bb.y, 0.f));
}

// ---------------- GEMM 2: h2 = g1 @ W2 (64->128), plus attention-logit epilogue ----------------
__global__ void gemm2_kernel(const float* __restrict__ W2,
                             const float* __restrict__ asrc, const float* __restrict__ adst,
                             int n) {
    __shared__ float Wsm[64 * 128];
    for (int i = threadIdx.x; i < 64 * 128; i += blockDim.x) Wsm[i] = W2[i];
    __syncthreads();
    int warp = threadIdx.x >> 5, lane = threadIdx.x & 31;
    const float2* Wp = (const float2*)Wsm;
    float2 as0 = ((const float2*)asrc)[lane], as1 = ((const float2*)asrc)[32 + lane];
    float2 ad0 = ((const float2*)adst)[lane], ad1 = ((const float2*)adst)[32 + lane];
    for (int row = blockIdx.x * 8 + warp; row < n; row += gridDim.x * 8) {
        const float* xr = d_g1 + (size_t)row * 64;
        float a00 = 0.f, a01 = 0.f, a10 = 0.f, a11 = 0.f;
#pragma unroll
        for (int c = 0; c < 2; c++) {
            float xv = xr[c * 32 + lane];
#pragma unroll
            for (int kk = 0; kk < 32; kk++) {
                float xb = __shfl_sync(FULL, xv, kk);
                int k = c * 32 + kk;
                float2 w0 = Wp[k * 64 + lane];
                float2 w1 = Wp[k * 64 + 32 + lane];
                a00 += xb * w0.x;
                a01 += xb * w0.y;
                a10 += xb * w1.x;
                a11 += xb * w1.y;
            }
        }
        ((float2*)d_h2)[row * 64 + lane] = make_float2(a00, a01);
        ((float2*)d_h2)[row * 64 + 32 + lane] = make_float2(a10, a11);
        float ps0 = a00 * as0.x + a01 * as0.y;
        float ps1 = a10 * as1.x + a11 * as1.y;
        float pd0 = a00 * ad0.x + a01 * ad0.y;
        float pd1 = a10 * ad1.x + a11 * ad1.y;
#pragma unroll
        for (int off = 16; off; off >>= 1) {
            ps0 += __shfl_xor_sync(FULL, ps0, off);
            ps1 += __shfl_xor_sync(FULL, ps1, off);
            pd0 += __shfl_xor_sync(FULL, pd0, off);
            pd1 += __shfl_xor_sync(FULL, pd1, off);
        }
        if (lane == 0) {
            d_als2[row] = make_float2(ps0, ps1);
            d_ald2[row] = make_float2(pd0, pd1);
        }
    }
}

// ---------------- GAT2 aggregation (2 heads, concat, relu) ----------------
__global__ void gat2_agg_kernel(const float* __restrict__ b2, int n) {
    int warp = threadIdx.x >> 5, lane = threadIdx.x & 31;
    int node = blockIdx.x * 8 + warp;
    if (node >= n) return;
    int beg = d_rowptr[node], end = d_rowptr[node + 1];
    float2 ad = d_ald2[node];
    // online softmax statistics, edge-strided across lanes
    float m0 = -1e30f, m1 = -1e30f, s0 = 0.f, s1 = 0.f;
    for (int e = beg + lane; e < end; e += 32) {
        int s = d_csrc[e];
        float2 as = d_als2[s];
        float e0 = leaky(as.x + ad.x);
        float e1 = leaky(as.y + ad.y);
        if (e0 > m0) { s0 = s0 * __expf(m0 - e0) + 1.f; m0 = e0; } else s0 += __expf(e0 - m0);
        if (e1 > m1) { s1 = s1 * __expf(m1 - e1) + 1.f; m1 = e1; } else s1 += __expf(e1 - m1);
    }
#pragma unroll
    for (int off = 16; off; off >>= 1) {
        float om = __shfl_xor_sync(FULL, m0, off);
        float os = __shfl_xor_sync(FULL, s0, off);
        float nm = fmaxf(m0, om);
        s0 = s0 * __expf(m0 - nm) + os * __expf(om - nm);
        m0 = nm;
        om = __shfl_xor_sync(FULL, m1, off);
        os = __shfl_xor_sync(FULL, s1, off);
        nm = fmaxf(m1, om);
        s1 = s1 * __expf(m1 - nm) + os * __expf(om - nm);
        m1 = nm;
    }
    float inv0 = 1.f / s0, inv1 = 1.f / s1;
    // weighted aggregation
    float h00 = 0.f, h01 = 0.f, h10 = 0.f, h11 = 0.f;
    const float2* H = (const float2*)d_h2;
    for (int base = beg; base < end; base += 32) {
        int rem = end - base;
        int my = 0;
        float w0 = 0.f, w1 = 0.f;
        if (lane < rem) {
            my = d_csrc[base + lane];
            float2 as = d_als2[my];
            float e0 = leaky(as.x + ad.x);
            float e1 = leaky(as.y + ad.y);
            w0 = __expf(e0 - m0) * inv0;
            w1 = __expf(e1 - m1) * inv1;
        }
        int cnt = rem < 32 ? rem : 32;
        for (int t = 0; t < cnt; t++) {
            int s = __shfl_sync(FULL, my, t);
            float ww0 = __shfl_sync(FULL, w0, t);
            float ww1 = __shfl_sync(FULL, w1, t);
            float2 v0 = H[s * 64 + lane];
            float2 v1 = H[s * 64 + 32 + lane];
            h00 += ww0 * v0.x;
            h01 += ww0 * v0.y;
            h10 += ww1 * v1.x;
            h11 += ww1 * v1.y;
        }
    }
    float2 bb0 = ((const float2*)b2)[lane];
    float2 bb1 = ((const float2*)b2)[32 + lane];
    ((float2*)d_g2)[node * 64 + lane] =
        make_float2(fmaxf(h00 + bb0.x, 0.f), fmaxf(h01 + bb0.y, 0.f));
    ((float2*)d_g2)[node * 64 + 32 + lane] =
        make_float2(fmaxf(h10 + bb1.x, 0.f), fmaxf(h11 + bb1.y, 0.f));
}

// ---------------- GEMM 3: h3 = g2 @ W3 (128->64), attention-logit epilogue (1 head) ----------------
__global__ void gemm3_kernel(const float* __restrict__ W3,
                             const float* __restrict__ asrc, const float* __restrict__ adst,
                             int n) {
    __shared__ float Wsm[128 * 64];
    for (int i = threadIdx.x; i < 128 * 64; i += blockDim.x) Wsm[i] = W3[i];
    __syncthreads();
    int warp = threadIdx.x >> 5, lane = threadIdx.x & 31;
    const float2* Wp = (const float2*)Wsm;
    float2 as = ((const float2*)asrc)[lane];
    float2 adw = ((const float2*)adst)[lane];
    for (int row = blockIdx.x * 8 + warp; row < n; row += gridDim.x * 8) {
        const float* xr = d_g2 + (size_t)row * 128;
        float a0 = 0.f, a1 = 0.f;
#pragma unroll
        for (int c = 0; c < 4; c++) {
            float xv = xr[c * 32 + lane];
#pragma unroll
            for (int kk = 0; kk < 32; kk++) {
                float xb = __shfl_sync(FULL, xv, kk);
                float2 w = Wp[(c * 32 + kk) * 32 + lane];
                a0 += xb * w.x;
                a1 += xb * w.y;
            }
        }
        ((float2*)d_h3)[row * 32 + lane] = make_float2(a0, a1);
        float ps = a0 * as.x + a1 * as.y;
        float pd = a0 * adw.x + a1 * adw.y;
#pragma unroll
        for (int off = 16; off; off >>= 1) {
            ps += __shfl_xor_sync(FULL, ps, off);
            pd += __shfl_xor_sync(FULL, pd, off);
        }
        if (lane == 0) {
            d_als3[row] = ps;
            d_ald3[row] = pd;
        }
    }
}

// ---------------- GAT3 aggregation (1 head, no relu) ----------------
__global__ void gat3_agg_kernel(const float* __restrict__ b3, int n) {
    int warp = threadIdx.x >> 5, lane = threadIdx.x & 31;
    int node = blockIdx.x * 8 + warp;
    if (node >= n) return;
    int beg = d_rowptr[node], end = d_rowptr[node + 1];
    float ad = d_ald3[node];
    float m = -1e30f, ssum = 0.f;
    for (int e = beg + lane; e < end; e += 32) {
        int s = d_csrc[e];
        float ev = leaky(d_als3[s] + ad);
        if (ev > m) { ssum = ssum * __expf(m - ev) + 1.f; m = ev; } else ssum += __expf(ev - m);
    }
#pragma unroll
    for (int off = 16; off; off >>= 1) {
        float om = __shfl_xor_sync(FULL, m, off);
        float os = __shfl_xor_sync(FULL, ssum, off);
        float nm = fmaxf(m, om);
        ssum = ssum * __expf(m - nm) + os * __expf(om - nm);
        m = nm;
    }
    float inv = 1.f / ssum;
    float a0 = 0.f, a1 = 0.f;
    const float2* H = (const float2*)d_h3;
    for (int base = beg; base < end; base += 32) {
        int rem = end - base;
        int my = 0;
        float w = 0.f;
        if (lane < rem) {
            my = d_csrc[base + lane];
            w = __expf(leaky(d_als3[my] + ad) - m) * inv;
        }
        int cnt = rem < 32 ? rem : 32;
        for (int t = 0; t < cnt; t++) {
            int s = __shfl_sync(FULL, my, t);
            float ww = __shfl_sync(FULL, w, t);
            float2 v = H[s * 32 + lane];
            a0 += ww * v.x;
            a1 += ww * v.y;
        }
    }
    float2 bb = ((const float2*)b3)[lane];
    ((float2*)d_g3)[node * 32 + lane] = make_float2(a0 + bb.x, a1 + bb.y);
}

// ---------------- graph boundaries from the sorted batch vector ----------------
__global__ void bounds_kernel(const void* batch, int n) {
    int is64 = g_is64;
    int i = blockIdx.x * blockDim.x + threadIdx.x;
    if (i >= n) return;
    int b = ld_idx(batch, i, is64);
    int pb = (i > 0) ? ld_idx(batch, i - 1, is64) : -1;
    for (int g = pb + 1; g <= b; ++g) d_start[g] = i;
}

// ---------------- mean-pool + fc + log_softmax ----------------
__global__ void pool_kernel(const float* __restrict__ Wfc, const float* __restrict__ bfc,
                            float* __restrict__ out) {
    int warp = threadIdx.x >> 5, lane = threadIdx.x & 31;
    int g = blockIdx.x * 8 + warp;
    if (g >= GG) return;
    int s0 = d_start[g], s1 = d_start[g + 1];
    float a0 = 0.f, a1 = 0.f;
    const float2* H = (const float2*)d_g3;
    for (int i = s0; i < s1; ++i) {
        float2 v = H[i * 32 + lane];
        a0 += v.x;
        a1 += v.y;
    }
    float inv = 1.f / fmaxf((float)(s1 - s0), 1.f);
    a0 *= inv;
    a1 *= inv;
    int c = 2 * lane;
    float l0 = a0 * Wfc[c * 2] + a1 * Wfc[(c + 1) * 2];
    float l1 = a0 * Wfc[c * 2 + 1] + a1 * Wfc[(c + 1) * 2 + 1];
#pragma unroll
    for (int off = 16; off; off >>= 1) {
        l0 += __shfl_xor_sync(FULL, l0, off);
        l1 += __shfl_xor_sync(FULL, l1, off);
    }
    if (lane == 0) {
        l0 += bfc[0];
        l1 += bfc[1];
        float mx = fmaxf(l0, l1);
        float lse = mx + logf(__expf(l0 - mx) + __expf(l1 - mx));
        out[g * 2] = l0 - lse;
        out[g * 2 + 1] = l1 - lse;
    }
}

// ---------------- host ----------------
extern "C" void kernel_launch(void* const* d_in, const int* in_sizes, int n_in,
                              void* d_out, int out_size) {
    const float* x    = (const float*)d_in[0];
    const void*  ei   = d_in[1];
    const void*  bat  = d_in[2];
    const float* W1   = (const float*)d_in[3];
    const float* b1   = (const float*)d_in[4];
    const float* W2   = (const float*)d_in[5];
    const float* as2  = (const float*)d_in[6];
    const float* ad2  = (const float*)d_in[7];
    const float* b2   = (const float*)d_in[8];
    const float* W3   = (const float*)d_in[9];
    const float* as3  = (const float*)d_in[10];
    const float* ad3  = (const float*)d_in[11];
    const float* b3   = (const float*)d_in[12];
    const float* Wfc  = (const float*)d_in[13];
    const float* bfc  = (const float*)d_in[14];
    float* out = (float*)d_out;

    const int n = in_sizes[0] / 128;   // 50000
    const int E = in_sizes[1] / 2;     // 800000

    const int GEMM_BLOCKS = 592;       // 4 per SM, W stays resident in L2/smem

    detect_kernel<<<1, 1>>>(ei);
    init_kernel<<<(n + 256) / 256 + 1, 256>>>(n);
    count_kernel<<<(E + 255) / 256, 256>>>(ei, E);
    scan_kernel<<<1, 1024>>>(n);
    scatter_kernel<<<(E + n + 255) / 256, 256>>>(ei, E, n);

    gemm1_kernel<<<GEMM_BLOCKS, 256>>>(x, W1, n);
    gcn_agg_kernel<<<(n + 7) / 8, 256>>>(b1, n);

    gemm2_kernel<<<GEMM_BLOCKS, 256>>>(W2, as2, ad2, n);
    gat2_agg_kernel<<<(n + 7) / 8, 256>>>(b2, n);

    gemm3_kernel<<<GEMM_BLOCKS, 256>>>(W3, as3, ad3, n);
    gat3_agg_kernel<<<(n + 7) / 8, 256>>>(b3, n);

    bounds_kernel<<<(n + 255) / 256, 256>>>(bat, n);
    pool_kernel<<<GG / 8, 256>>>(Wfc, bfc, out);
    (void)n_in; (void)out_size;
}

// round 4
// speedup vs baseline: 1.2808x; 1.2808x over previous
#include <cuda_runtime.h>
#include <math.h>

#define NN 50000
#define EE 800000
#define ETOT (EE + NN)
#define GG 512
#define FULL 0xffffffffu
#define SCAN_B 512
#define NB_MAX ((NN + SCAN_B - 1) / SCAN_B)   // 98

// ---------------- scratch (device globals: the sanctioned allocation-free path) ----
__device__ int   g_is64;
__device__ int   d_cnt[NN];
__device__ int   d_rowptr[NN + 1];
__device__ int   d_cursor[NN];
__device__ float d_dis[NN];
__device__ int   d_bsum[128];
__device__ int   d_boff[128];
__device__ int   d_csrc[ETOT];
__device__ float d_h1s[NN * 64];     // (x@W1)*dis
__device__ float d_g1[NN * 64];      // relu(GCN out)
__device__ float d_h2[NN * 128];     // g1@W2
__device__ float2 d_als2[NN];
__device__ float2 d_ald2[NN];
__device__ float d_g2[NN * 128];     // relu(GAT2 out)
__device__ float d_h3[NN * 64];      // g2@W3
__device__ float d_als3[NN];
__device__ float d_ald3[NN];
__device__ float d_g3[NN * 64];      // GAT3 out
__device__ int   d_start[GG + 1];

// ---------------- helpers ----------------
__device__ __forceinline__ int ld_idx(const void* p, int i, int is64) {
    return is64 ? (int)((const long long*)p)[i] : ((const int*)p)[i];
}
__device__ __forceinline__ float leaky(float v) { return v > 0.f ? v : 0.2f * v; }

// block-wide exclusive scan (blockDim.x <= 1024, multiple of 32); smem: int[32]
__device__ __forceinline__ int block_excl_scan(int v, int* wsum) {
    int lane = threadIdx.x & 31, wid = threadIdx.x >> 5;
    int inc = v;
#pragma unroll
    for (int off = 1; off < 32; off <<= 1) {
        int t = __shfl_up_sync(FULL, inc, off);
        if (lane >= off) inc += t;
    }
    if (lane == 31) wsum[wid] = inc;
    __syncthreads();
    if (wid == 0) {
        int nw = blockDim.x >> 5;
        int s = (lane < nw) ? wsum[lane] : 0;
#pragma unroll
        for (int off = 1; off < 32; off <<= 1) {
            int t = __shfl_up_sync(FULL, s, off);
            if (lane >= off) s += t;
        }
        wsum[lane] = s;
    }
    __syncthreads();
    int base = (wid > 0) ? wsum[wid - 1] : 0;
    return base + inc - v;
}

// ---------------- index-width detection ----------------
__global__ void detect_kernel(const void* ei) {
    const long long* p = (const long long*)ei;
    int ok = 1;
#pragma unroll
    for (int i = 0; i < 4; i++) {
        long long v = p[i];
        if (v < 0 || v >= NN) ok = 0;
    }
    g_is64 = ok;
}

// ---------------- CSR build ----------------
__global__ void init_kernel(int n) {
    int i = blockIdx.x * blockDim.x + threadIdx.x;
    if (i < n) d_cnt[i] = 1;            // self-loop
    if (i <= GG) d_start[i] = n;        // default boundary (empty graphs)
}

__global__ void count_kernel(const void* ei, int E) {
    int is64 = g_is64;
    int e = blockIdx.x * blockDim.x + threadIdx.x;
    if (e < E) {
        int d = ld_idx(ei, E + e, is64);
        atomicAdd(&d_cnt[d], 1);
    }
}

// scan phase A: per-tile sums
__global__ void scanA_kernel(int n) {
    __shared__ int wsum[32];
    int i = blockIdx.x * SCAN_B + threadIdx.x;
    int v = (i < n) ? d_cnt[i] : 0;
    int lane = threadIdx.x & 31, wid = threadIdx.x >> 5;
#pragma unroll
    for (int off = 16; off; off >>= 1) v += __shfl_down_sync(FULL, v, off);
    if (lane == 0) wsum[wid] = v;
    __syncthreads();
    if (wid == 0) {
        int nw = blockDim.x >> 5;
        int s = (lane < nw) ? wsum[lane] : 0;
#pragma unroll
        for (int off = 16; off; off >>= 1) s += __shfl_down_sync(FULL, s, off);
        if (lane == 0) d_bsum[blockIdx.x] = s;
    }
}

// scan phase B: exclusive scan of the <=128 tile sums (one block)
__global__ void scanB_kernel(int nb, int n) {
    __shared__ int wsum[32];
    int t = threadIdx.x;
    int v = (t < nb) ? d_bsum[t] : 0;
    int ex = block_excl_scan(v, wsum);
    if (t < nb) d_boff[t] = ex;
    if (t == nb - 1) d_rowptr[n] = ex + v;
}

// scan phase C: per-tile exclusive scan + rowptr/cursor/dis writes
__global__ void scanC_kernel(int n) {
    __shared__ int wsum[32];
    int i = blockIdx.x * SCAN_B + threadIdx.x;
    int c = (i < n) ? d_cnt[i] : 0;
    int ex = block_excl_scan(c, wsum);
    if (i < n) {
        int p = d_boff[blockIdx.x] + ex;
        d_rowptr[i] = p;
        d_cursor[i] = p;
        d_dis[i] = rsqrtf((float)c);
    }
}

__global__ void scatter_kernel(const void* ei, int E, int n) {
    int is64 = g_is64;
    int t = blockIdx.x * blockDim.x + threadIdx.x;
    if (t < E) {
        int s = ld_idx(ei, t, is64);
        int d = ld_idx(ei, E + t, is64);
        int pos = atomicAdd(&d_cursor[d], 1);
        d_csrc[pos] = s;
    } else if (t < E + n) {
        int i = t - E;
        int pos = atomicAdd(&d_cursor[i], 1);
        d_csrc[pos] = i;
    }
}

// ---------------- GEMM 1: h1s = (x @ W1) * dis,   x[N,128], W1[128,64] ----------------
__global__ void gemm1_kernel(const float* __restrict__ x, const float* __restrict__ W1, int n) {
    __shared__ float Wsm[128 * 64];
    for (int i = threadIdx.x; i < 128 * 64; i += blockDim.x) Wsm[i] = W1[i];
    __syncthreads();
    int warp = threadIdx.x >> 5, lane = threadIdx.x & 31;
    const float2* Wp = (const float2*)Wsm;
    for (int row = blockIdx.x * 8 + warp; row < n; row += gridDim.x * 8) {
        const float* xr = x + (size_t)row * 128;
        float a0 = 0.f, a1 = 0.f;
#pragma unroll
        for (int c = 0; c < 4; c++) {
            float xv = xr[c * 32 + lane];
#pragma unroll
            for (int kk = 0; kk < 32; kk++) {
                float xb = __shfl_sync(FULL, xv, kk);
                float2 w = Wp[(c * 32 + kk) * 32 + lane];
                a0 += xb * w.x;
                a1 += xb * w.y;
            }
        }
        float d = d_dis[row];
        ((float2*)d_h1s)[row * 32 + lane] = make_float2(a0 * d, a1 * d);
    }
}

// ---------------- GCN aggregation: g1 = relu(dis * sum_src h1s[src] + b1) ----------------
__global__ void gcn_agg_kernel(const float* __restrict__ b1, int n) {
    int warp = threadIdx.x >> 5, lane = threadIdx.x & 31;
    int node = blockIdx.x * 8 + warp;
    if (node >= n) return;
    int beg = d_rowptr[node], end = d_rowptr[node + 1];
    float a0 = 0.f, a1 = 0.f;
    const float2* H = (const float2*)d_h1s;
    for (int base = beg; base < end; base += 32) {
        int rem = end - base;
        int my = (lane < rem) ? d_csrc[base + lane] : 0;
        int cnt = rem < 32 ? rem : 32;
        for (int t = 0; t < cnt; t++) {
            int s = __shfl_sync(FULL, my, t);
            float2 v = H[s * 32 + lane];
            a0 += v.x;
            a1 += v.y;
        }
    }
    float d = d_dis[node];
    float2 bb = ((const float2*)b1)[lane];
    ((float2*)d_g1)[node * 32 + lane] =
        make_float2(fmaxf(a0 * d + bb.x, 0.f), fmaxf(a1 * d + bb.y, 0.f));
}

// ---------------- GEMM 2: h2 = g1 @ W2 (64->128), plus attention-logit epilogue ----------------
__global__ void gemm2_kernel(const float* __restrict__ W2,
                             const float* __restrict__ asrc, const float* __restrict__ adst,
                             int n) {
    __shared__ float Wsm[64 * 128];
    for (int i = threadIdx.x; i < 64 * 128; i += blockDim.x) Wsm[i] = W2[i];
    __syncthreads();
    int warp = threadIdx.x >> 5, lane = threadIdx.x & 31;
    const float2* Wp = (const float2*)Wsm;
    float2 as0 = ((const float2*)asrc)[lane], as1 = ((const float2*)asrc)[32 + lane];
    float2 ad0 = ((const float2*)adst)[lane], ad1 = ((const float2*)adst)[32 + lane];
    for (int row = blockIdx.x * 8 + warp; row < n; row += gridDim.x * 8) {
        const float* xr = d_g1 + (size_t)row * 64;
        float a00 = 0.f, a01 = 0.f, a10 = 0.f, a11 = 0.f;
#pragma unroll
        for (int c = 0; c < 2; c++) {
            float xv = xr[c * 32 + lane];
#pragma unroll
            for (int kk = 0; kk < 32; kk++) {
                float xb = __shfl_sync(FULL, xv, kk);
                int k = c * 32 + kk;
                float2 w0 = Wp[k * 64 + lane];
                float2 w1 = Wp[k * 64 + 32 + lane];
                a00 += xb * w0.x;
                a01 += xb * w0.y;
                a10 += xb * w1.x;
                a11 += xb * w1.y;
            }
        }
        ((float2*)d_h2)[row * 64 + lane] = make_float2(a00, a01);
        ((float2*)d_h2)[row * 64 + 32 + lane] = make_float2(a10, a11);
        float ps0 = a00 * as0.x + a01 * as0.y;
        float ps1 = a10 * as1.x + a11 * as1.y;
        float pd0 = a00 * ad0.x + a01 * ad0.y;
        float pd1 = a10 * ad1.x + a11 * ad1.y;
#pragma unroll
        for (int off = 16; off; off >>= 1) {
            ps0 += __shfl_xor_sync(FULL, ps0, off);
            ps1 += __shfl_xor_sync(FULL, ps1, off);
            pd0 += __shfl_xor_sync(FULL, pd0, off);
            pd1 += __shfl_xor_sync(FULL, pd1, off);
        }
        if (lane == 0) {
            d_als2[row] = make_float2(ps0, ps1);
            d_ald2[row] = make_float2(pd0, pd1);
        }
    }
}

// ---------------- GAT2 aggregation (2 heads, concat, relu) ----------------
__global__ void gat2_agg_kernel(const float* __restrict__ b2, int n) {
    int warp = threadIdx.x >> 5, lane = threadIdx.x & 31;
    int node = blockIdx.x * 8 + warp;
    if (node >= n) return;
    int beg = d_rowptr[node], end = d_rowptr[node + 1];
    float2 ad = d_ald2[node];
    // online softmax statistics, edge-strided across lanes
    float m0 = -1e30f, m1 = -1e30f, s0 = 0.f, s1 = 0.f;
    for (int e = beg + lane; e < end; e += 32) {
        int s = d_csrc[e];
        float2 as = d_als2[s];
        float e0 = leaky(as.x + ad.x);
        float e1 = leaky(as.y + ad.y);
        if (e0 > m0) { s0 = s0 * __expf(m0 - e0) + 1.f; m0 = e0; } else s0 += __expf(e0 - m0);
        if (e1 > m1) { s1 = s1 * __expf(m1 - e1) + 1.f; m1 = e1; } else s1 += __expf(e1 - m1);
    }
#pragma unroll
    for (int off = 16; off; off >>= 1) {
        float om = __shfl_xor_sync(FULL, m0, off);
        float os = __shfl_xor_sync(FULL, s0, off);
        float nm = fmaxf(m0, om);
        s0 = s0 * __expf(m0 - nm) + os * __expf(om - nm);
        m0 = nm;
        om = __shfl_xor_sync(FULL, m1, off);
        os = __shfl_xor_sync(FULL, s1, off);
        nm = fmaxf(m1, om);
        s1 = s1 * __expf(m1 - nm) + os * __expf(om - nm);
        m1 = nm;
    }
    float inv0 = 1.f / s0, inv1 = 1.f / s1;
    // weighted aggregation
    float h00 = 0.f, h01 = 0.f, h10 = 0.f, h11 = 0.f;
    const float2* H = (const float2*)d_h2;
    for (int base = beg; base < end; base += 32) {
        int rem = end - base;
        int my = 0;
        float w0 = 0.f, w1 = 0.f;
        if (lane < rem) {
            my = d_csrc[base + lane];
            float2 as = d_als2[my];
            float e0 = leaky(as.x + ad.x);
            float e1 = leaky(as.y + ad.y);
            w0 = __expf(e0 - m0) * inv0;
            w1 = __expf(e1 - m1) * inv1;
        }
        int cnt = rem < 32 ? rem : 32;
        for (int t = 0; t < cnt; t++) {
            int s = __shfl_sync(FULL, my, t);
            float ww0 = __shfl_sync(FULL, w0, t);
            float ww1 = __shfl_sync(FULL, w1, t);
            float2 v0 = H[s * 64 + lane];
            float2 v1 = H[s * 64 + 32 + lane];
            h00 += ww0 * v0.x;
            h01 += ww0 * v0.y;
            h10 += ww1 * v1.x;
            h11 += ww1 * v1.y;
        }
    }
    float2 bb0 = ((const float2*)b2)[lane];
    float2 bb1 = ((const float2*)b2)[32 + lane];
    ((float2*)d_g2)[node * 64 + lane] =
        make_float2(fmaxf(h00 + bb0.x, 0.f), fmaxf(h01 + bb0.y, 0.f));
    ((float2*)d_g2)[node * 64 + 32 + lane] =
        make_float2(fmaxf(h10 + bb1.x, 0.f), fmaxf(h11 + bb1.y, 0.f));
}

// ---------------- GEMM 3: h3 = g2 @ W3 (128->64), attention-logit epilogue (1 head) ----------------
__global__ void gemm3_kernel(const float* __restrict__ W3,
                             const float* __restrict__ asrc, const float* __restrict__ adst,
                             int n) {
    __shared__ float Wsm[128 * 64];
    for (int i = threadIdx.x; i < 128 * 64; i += blockDim.x) Wsm[i] = W3[i];
    __syncthreads();
    int warp = threadIdx.x >> 5, lane = threadIdx.x & 31;
    const float2* Wp = (const float2*)Wsm;
    float2 as = ((const float2*)asrc)[lane];
    float2 adw = ((const float2*)adst)[lane];
    for (int row = blockIdx.x * 8 + warp; row < n; row += gridDim.x * 8) {
        const float* xr = d_g2 + (size_t)row * 128;
        float a0 = 0.f, a1 = 0.f;
#pragma unroll
        for (int c = 0; c < 4; c++) {
            float xv = xr[c * 32 + lane];
#pragma unroll
            for (int kk = 0; kk < 32; kk++) {
                float xb = __shfl_sync(FULL, xv, kk);
                float2 w = Wp[(c * 32 + kk) * 32 + lane];
                a0 += xb * w.x;
                a1 += xb * w.y;
            }
        }
        ((float2*)d_h3)[row * 32 + lane] = make_float2(a0, a1);
        float ps = a0 * as.x + a1 * as.y;
        float pd = a0 * adw.x + a1 * adw.y;
#pragma unroll
        for (int off = 16; off; off >>= 1) {
            ps += __shfl_xor_sync(FULL, ps, off);
            pd += __shfl_xor_sync(FULL, pd, off);
        }
        if (lane == 0) {
            d_als3[row] = ps;
            d_ald3[row] = pd;
        }
    }
}

// ---------------- GAT3 aggregation (1 head, no relu) ----------------
__global__ void gat3_agg_kernel(const float* __restrict__ b3, int n) {
    int warp = threadIdx.x >> 5, lane = threadIdx.x & 31;
    int node = blockIdx.x * 8 + warp;
    if (node >= n) return;
    int beg = d_rowptr[node], end = d_rowptr[node + 1];
    float ad = d_ald3[node];
    float m = -1e30f, ssum = 0.f;
    for (int e = beg + lane; e < end; e += 32) {
        int s = d_csrc[e];
        float ev = leaky(d_als3[s] + ad);
        if (ev > m) { ssum = ssum * __expf(m - ev) + 1.f; m = ev; } else ssum += __expf(ev - m);
    }
#pragma unroll
    for (int off = 16; off; off >>= 1) {
        float om = __shfl_xor_sync(FULL, m, off);
        float os = __shfl_xor_sync(FULL, ssum, off);
        float nm = fmaxf(m, om);
        ssum = ssum * __expf(m - nm) + os * __expf(om - nm);
        m = nm;
    }
    float inv = 1.f / ssum;
    float a0 = 0.f, a1 = 0.f;
    const float2* H = (const float2*)d_h3;
    for (int base = beg; base < end; base += 32) {
        int rem = end - base;
        int my = 0;
        float w = 0.f;
        if (lane < rem) {
            my = d_csrc[base + lane];
            w = __expf(leaky(d_als3[my] + ad) - m) * inv;
        }
        int cnt = rem < 32 ? rem : 32;
        for (int t = 0; t < cnt; t++) {
            int s = __shfl_sync(FULL, my, t);
            float ww = __shfl_sync(FULL, w, t);
            float2 v = H[s * 32 + lane];
            a0 += ww * v.x;
            a1 += ww * v.y;
        }
    }
    float2 bb = ((const float2*)b3)[lane];
    ((float2*)d_g3)[node * 32 + lane] = make_float2(a0 + bb.x, a1 + bb.y);
}

// ---------------- graph boundaries from the sorted batch vector ----------------
__global__ void bounds_kernel(const void* batch, int n) {
    int is64 = g_is64;
    int i = blockIdx.x * blockDim.x + threadIdx.x;
    if (i >= n) return;
    int b = ld_idx(batch, i, is64);
    int pb = (i > 0) ? ld_idx(batch, i - 1, is64) : -1;
    for (int g = pb + 1; g <= b; ++g) d_start[g] = i;
}

// ---------------- mean-pool + fc + log_softmax ----------------
__global__ void pool_kernel(const float* __restrict__ Wfc, const float* __restrict__ bfc,
                            float* __restrict__ out) {
    int warp = threadIdx.x >> 5, lane = threadIdx.x & 31;
    int g = blockIdx.x * 8 + warp;
    if (g >= GG) return;
    int s0 = d_start[g], s1 = d_start[g + 1];
    float a0 = 0.f, a1 = 0.f;
    const float2* H = (const float2*)d_g3;
    for (int i = s0; i < s1; ++i) {
        float2 v = H[i * 32 + lane];
        a0 += v.x;
        a1 += v.y;
    }
    float inv = 1.f / fmaxf((float)(s1 - s0), 1.f);
    a0 *= inv;
    a1 *= inv;
    int c = 2 * lane;
    float l0 = a0 * Wfc[c * 2] + a1 * Wfc[(c + 1) * 2];
    float l1 = a0 * Wfc[c * 2 + 1] + a1 * Wfc[(c + 1) * 2 + 1];
#pragma unroll
    for (int off = 16; off; off >>= 1) {
        l0 += __shfl_xor_sync(FULL, l0, off);
        l1 += __shfl_xor_sync(FULL, l1, off);
    }
    if (lane == 0) {
        l0 += bfc[0];
        l1 += bfc[1];
        float mx = fmaxf(l0, l1);
        float lse = mx + logf(__expf(l0 - mx) + __expf(l1 - mx));
        out[g * 2] = l0 - lse;
        out[g * 2 + 1] = l1 - lse;
    }
}

// ---------------- host ----------------
extern "C" void kernel_launch(void* const* d_in, const int* in_sizes, int n_in,
                              void* d_out, int out_size) {
    const float* x    = (const float*)d_in[0];
    const void*  ei   = d_in[1];
    const void*  bat  = d_in[2];
    const float* W1   = (const float*)d_in[3];
    const float* b1   = (const float*)d_in[4];
    const float* W2   = (const float*)d_in[5];
    const float* as2  = (const float*)d_in[6];
    const float* ad2  = (const float*)d_in[7];
    const float* b2   = (const float*)d_in[8];
    const float* W3   = (const float*)d_in[9];
    const float* as3  = (const float*)d_in[10];
    const float* ad3  = (const float*)d_in[11];
    const float* b3   = (const float*)d_in[12];
    const float* Wfc  = (const float*)d_in[13];
    const float* bfc  = (const float*)d_in[14];
    float* out = (float*)d_out;

    const int n = in_sizes[0] / 128;   // 50000
    const int E = in_sizes[1] / 2;     // 800000
    const int nb = (n + SCAN_B - 1) / SCAN_B;  // 98

    const int GEMM_BLOCKS = 592;       // 4 per SM, W stays resident in L2/smem

    detect_kernel<<<1, 1>>>(ei);
    init_kernel<<<(n + 256) / 256 + 1, 256>>>(n);
    count_kernel<<<(E + 255) / 256, 256>>>(ei, E);
    scanA_kernel<<<nb, SCAN_B>>>(n);
    scanB_kernel<<<1, 128>>>(nb, n);
    scanC_kernel<<<nb, SCAN_B>>>(n);
    scatter_kernel<<<(E + n + 255) / 256, 256>>>(ei, E, n);

    gemm1_kernel<<<GEMM_BLOCKS, 256>>>(x, W1, n);
    gcn_agg_kernel<<<(n + 7) / 8, 256>>>(b1, n);

    gemm2_kernel<<<GEMM_BLOCKS, 256>>>(W2, as2, ad2, n);
    gat2_agg_kernel<<<(n + 7) / 8, 256>>>(b2, n);

    gemm3_kernel<<<GEMM_BLOCKS, 256>>>(W3, as3, ad3, n);
    gat3_agg_kernel<<<(n + 7) / 8, 256>>>(b3, n);

    bounds_kernel<<<(n + 255) / 256, 256>>>(bat, n);
    pool_kernel<<<GG / 8, 256>>>(Wfc, bfc, out);
    (void)n_in; (void)out_size;
}

// round 5
// speedup vs baseline: 1.3325x; 1.0404x over previous
#include <cuda_runtime.h>
#include <math.h>

#define NN 50000
#define EE 800000
#define ETOT (EE + NN)
#define GG 512
#define FULL 0xffffffffu
#define SCAN_B 512

// ---------------- scratch (device globals) ----------------
__device__ int   g_is64;
__device__ int   d_cnt[NN];
__device__ int   d_rowptr[NN + 1];
__device__ int   d_cursor[NN];
__device__ float d_dis[NN];
__device__ int   d_bsum[128];
__device__ int   d_boff[128];
__device__ int   d_csrc[ETOT];
__device__ float d_h1s[NN * 64];     // (x@W1)*dis[src]
__device__ float d_h2[NN * 128];     // (gcn-out)@W2
__device__ float2 d_als2[NN];
__device__ float2 d_ald2[NN];
__device__ float d_h3[NN * 64];      // (gat2-out)@W3
__device__ float d_als3[NN];
__device__ float d_ald3[NN];
__device__ float d_g3[NN * 64];      // GAT3 out
__device__ int   d_start[GG + 1];

// ---------------- helpers ----------------
__device__ __forceinline__ int ld_idx(const void* p, int i, int is64) {
    return is64 ? (int)((const long long*)p)[i] : ((const int*)p)[i];
}
__device__ __forceinline__ float leaky(float v) { return v > 0.f ? v : 0.2f * v; }

__device__ __forceinline__ int block_excl_scan(int v, int* wsum) {
    int lane = threadIdx.x & 31, wid = threadIdx.x >> 5;
    int inc = v;
#pragma unroll
    for (int off = 1; off < 32; off <<= 1) {
        int t = __shfl_up_sync(FULL, inc, off);
        if (lane >= off) inc += t;
    }
    if (lane == 31) wsum[wid] = inc;
    __syncthreads();
    if (wid == 0) {
        int nw = blockDim.x >> 5;
        int s = (lane < nw) ? wsum[lane] : 0;
#pragma unroll
        for (int off = 1; off < 32; off <<= 1) {
            int t = __shfl_up_sync(FULL, s, off);
            if (lane >= off) s += t;
        }
        wsum[lane] = s;
    }
    __syncthreads();
    int base = (wid > 0) ? wsum[wid - 1] : 0;
    return base + inc - v;
}

// ---------------- index-width detection ----------------
__global__ void detect_kernel(const void* ei) {
    const long long* p = (const long long*)ei;
    int ok = 1;
#pragma unroll
    for (int i = 0; i < 4; i++) {
        long long v = p[i];
        if (v < 0 || v >= NN) ok = 0;
    }
    g_is64 = ok;
}

// ---------------- CSR build ----------------
__global__ void init_kernel(int n) {
    int i = blockIdx.x * blockDim.x + threadIdx.x;
    if (i < n) d_cnt[i] = 1;            // self-loop
    if (i <= GG) d_start[i] = n;
}

__global__ void count_kernel(const void* ei, int E) {
    int is64 = g_is64;
    int e = blockIdx.x * blockDim.x + threadIdx.x;
    if (e < E) {
        int d = ld_idx(ei, E + e, is64);
        atomicAdd(&d_cnt[d], 1);
    }
}

__global__ void scanA_kernel(int n) {
    __shared__ int wsum[32];
    int i = blockIdx.x * SCAN_B + threadIdx.x;
    int v = (i < n) ? d_cnt[i] : 0;
    int lane = threadIdx.x & 31, wid = threadIdx.x >> 5;
#pragma unroll
    for (int off = 16; off; off >>= 1) v += __shfl_down_sync(FULL, v, off);
    if (lane == 0) wsum[wid] = v;
    __syncthreads();
    if (wid == 0) {
        int nw = blockDim.x >> 5;
        int s = (lane < nw) ? wsum[lane] : 0;
#pragma unroll
        for (int off = 16; off; off >>= 1) s += __shfl_down_sync(FULL, s, off);
        if (lane == 0) d_bsum[blockIdx.x] = s;
    }
}

__global__ void scanB_kernel(int nb, int n) {
    __shared__ int wsum[32];
    int t = threadIdx.x;
    int v = (t < nb) ? d_bsum[t] : 0;
    int ex = block_excl_scan(v, wsum);
    if (t < nb) d_boff[t] = ex;
    if (t == nb - 1) d_rowptr[n] = ex + v;
}

__global__ void scanC_kernel(int n) {
    __shared__ int wsum[32];
    int i = blockIdx.x * SCAN_B + threadIdx.x;
    int c = (i < n) ? d_cnt[i] : 0;
    int ex = block_excl_scan(c, wsum);
    if (i < n) {
        int p = d_boff[blockIdx.x] + ex;
        d_rowptr[i] = p;
        d_cursor[i] = p;
        d_dis[i] = rsqrtf((float)c);
    }
}

__global__ void scatter_kernel(const void* ei, int E, int n) {
    int is64 = g_is64;
    int t = blockIdx.x * blockDim.x + threadIdx.x;
    if (t < E) {
        int s = ld_idx(ei, t, is64);
        int d = ld_idx(ei, E + t, is64);
        int pos = atomicAdd(&d_cursor[d], 1);
        d_csrc[pos] = s;
    } else if (t < E + n) {
        int i = t - E;
        int pos = atomicAdd(&d_cursor[i], 1);
        d_csrc[pos] = i;
    }
}

// ---------------- GEMM 1: h1s = (x @ W1) * dis ----------------
__global__ void __launch_bounds__(256) gemm1_kernel(const float* __restrict__ x,
                                                    const float* __restrict__ W1, int n) {
    __shared__ float Wsm[128 * 64];
    for (int i = threadIdx.x; i < 128 * 64; i += blockDim.x) Wsm[i] = W1[i];
    __syncthreads();
    int warp = threadIdx.x >> 5, lane = threadIdx.x & 31;
    const float2* Wp = (const float2*)Wsm;
    for (int row = blockIdx.x * 8 + warp; row < n; row += gridDim.x * 8) {
        const float* xr = x + (size_t)row * 128;
        float a0 = 0.f, a1 = 0.f;
#pragma unroll
        for (int c = 0; c < 4; c++) {
            float xv = xr[c * 32 + lane];
#pragma unroll
            for (int kk = 0; kk < 32; kk++) {
                float xb = __shfl_sync(FULL, xv, kk);
                float2 w = Wp[(c * 32 + kk) * 32 + lane];
                a0 += xb * w.x;
                a1 += xb * w.y;
            }
        }
        float d = d_dis[row];
        ((float2*)d_h1s)[row * 32 + lane] = make_float2(a0 * d, a1 * d);
    }
}

// ---- fused: GCN aggregate (-> g1 row in regs) then GEMM2 + attention epilogue ----
__global__ void __launch_bounds__(256) fused_gcn_gemm2_kernel(
    const float* __restrict__ W2, const float* __restrict__ b1,
    const float* __restrict__ asrc, const float* __restrict__ adst, int n) {
    __shared__ float Wsm[64 * 128];
    for (int i = threadIdx.x; i < 64 * 128; i += blockDim.x) Wsm[i] = W2[i];
    __syncthreads();
    int warp = threadIdx.x >> 5, lane = threadIdx.x & 31;
    const float2* Wp = (const float2*)Wsm;
    float2 as0 = ((const float2*)asrc)[lane], as1 = ((const float2*)asrc)[32 + lane];
    float2 ad0 = ((const float2*)adst)[lane], ad1 = ((const float2*)adst)[32 + lane];
    float2 bb = ((const float2*)b1)[lane];
    const float2* H = (const float2*)d_h1s;

    for (int node = blockIdx.x * 8 + warp; node < n; node += gridDim.x * 8) {
        int beg = d_rowptr[node], end = d_rowptr[node + 1];
        float a0 = 0.f, a1 = 0.f;
        int e = beg;
        for (; e + 32 <= end; e += 32) {
            int my = d_csrc[e + lane];
#pragma unroll
            for (int t = 0; t < 32; t++) {
                int s = __shfl_sync(FULL, my, t);
                float2 v = H[s * 32 + lane];
                a0 += v.x;
                a1 += v.y;
            }
        }
        if (e < end) {
            int rem = end - e;
            int my = (lane < rem) ? d_csrc[e + lane] : 0;
            for (int t = 0; t < rem; t++) {
                int s = __shfl_sync(FULL, my, t);
                float2 v = H[s * 32 + lane];
                a0 += v.x;
                a1 += v.y;
            }
        }
        float d = d_dis[node];
        float gx = fmaxf(a0 * d + bb.x, 0.f);   // g1[k], k = 2*lane
        float gy = fmaxf(a1 * d + bb.y, 0.f);   // g1[k], k = 2*lane+1

        // GEMM2: h2 = g1 @ W2  (64 -> 128)
        float a00 = 0.f, a01 = 0.f, a10 = 0.f, a11 = 0.f;
#pragma unroll
        for (int kk = 0; kk < 32; kk++) {
            float xb0 = __shfl_sync(FULL, gx, kk);        // k = 2kk
            float xb1 = __shfl_sync(FULL, gy, kk);        // k = 2kk+1
            float2 w00 = Wp[(2 * kk) * 64 + lane];
            float2 w01 = Wp[(2 * kk) * 64 + 32 + lane];
            float2 w10 = Wp[(2 * kk + 1) * 64 + lane];
            float2 w11 = Wp[(2 * kk + 1) * 64 + 32 + lane];
            a00 += xb0 * w00.x + xb1 * w10.x;
            a01 += xb0 * w00.y + xb1 * w10.y;
            a10 += xb0 * w01.x + xb1 * w11.x;
            a11 += xb0 * w01.y + xb1 * w11.y;
        }
        ((float2*)d_h2)[node * 64 + lane] = make_float2(a00, a01);
        ((float2*)d_h2)[node * 64 + 32 + lane] = make_float2(a10, a11);
        float ps0 = a00 * as0.x + a01 * as0.y;
        float ps1 = a10 * as1.x + a11 * as1.y;
        float pd0 = a00 * ad0.x + a01 * ad0.y;
        float pd1 = a10 * ad1.x + a11 * ad1.y;
#pragma unroll
        for (int off = 16; off; off >>= 1) {
            ps0 += __shfl_xor_sync(FULL, ps0, off);
            ps1 += __shfl_xor_sync(FULL, ps1, off);
            pd0 += __shfl_xor_sync(FULL, pd0, off);
            pd1 += __shfl_xor_sync(FULL, pd1, off);
        }
        if (lane == 0) {
            d_als2[node] = make_float2(ps0, ps1);
            d_ald2[node] = make_float2(pd0, pd1);
        }
    }
}

// ---- fused: GAT2 aggregate (2 heads, relu -> g2 row in regs) then GEMM3 + epilogue ----
__global__ void __launch_bounds__(256) fused_gat2_gemm3_kernel(
    const float* __restrict__ W3, const float* __restrict__ b2,
    const float* __restrict__ asrc, const float* __restrict__ adst, int n) {
    __shared__ float Wsm[128 * 64];
    for (int i = threadIdx.x; i < 128 * 64; i += blockDim.x) Wsm[i] = W3[i];
    __syncthreads();
    int warp = threadIdx.x >> 5, lane = threadIdx.x & 31;
    const float2* Wp = (const float2*)Wsm;
    float2 as3 = ((const float2*)asrc)[lane];
    float2 ad3 = ((const float2*)adst)[lane];
    float2 bb0 = ((const float2*)b2)[lane];
    float2 bb1 = ((const float2*)b2)[32 + lane];
    const float2* H = (const float2*)d_h2;

    for (int node = blockIdx.x * 8 + warp; node < n; node += gridDim.x * 8) {
        int beg = d_rowptr[node], end = d_rowptr[node + 1];
        float2 ad = d_ald2[node];

        // pass 1: online softmax stats over incoming edges
        float m0 = -1e30f, m1 = -1e30f, s0 = 0.f, s1 = 0.f;
        for (int e = beg + lane; e < end; e += 32) {
            int s = d_csrc[e];
            float2 as = d_als2[s];
            float e0 = leaky(as.x + ad.x);
            float e1 = leaky(as.y + ad.y);
            if (e0 > m0) { s0 = s0 * __expf(m0 - e0) + 1.f; m0 = e0; } else s0 += __expf(e0 - m0);
            if (e1 > m1) { s1 = s1 * __expf(m1 - e1) + 1.f; m1 = e1; } else s1 += __expf(e1 - m1);
        }
#pragma unroll
        for (int off = 16; off; off >>= 1) {
            float om = __shfl_xor_sync(FULL, m0, off);
            float os = __shfl_xor_sync(FULL, s0, off);
            float nm = fmaxf(m0, om);
            s0 = s0 * __expf(m0 - nm) + os * __expf(om - nm);
            m0 = nm;
            om = __shfl_xor_sync(FULL, m1, off);
            os = __shfl_xor_sync(FULL, s1, off);
            nm = fmaxf(m1, om);
            s1 = s1 * __expf(m1 - nm) + os * __expf(om - nm);
            m1 = nm;
        }
        float inv0 = 1.f / s0, inv1 = 1.f / s1;

        // pass 2: weighted aggregation
        float h00 = 0.f, h01 = 0.f, h10 = 0.f, h11 = 0.f;
        int e = beg;
        for (; e + 32 <= end; e += 32) {
            int my = d_csrc[e + lane];
            float2 as = d_als2[my];
            float w0 = __expf(leaky(as.x + ad.x) - m0) * inv0;
            float w1 = __expf(leaky(as.y + ad.y) - m1) * inv1;
#pragma unroll 16
            for (int t = 0; t < 32; t++) {
                int s = __shfl_sync(FULL, my, t);
                float ww0 = __shfl_sync(FULL, w0, t);
                float ww1 = __shfl_sync(FULL, w1, t);
                float2 v0 = H[s * 64 + lane];
                float2 v1 = H[s * 64 + 32 + lane];
                h00 += ww0 * v0.x;
                h01 += ww0 * v0.y;
                h10 += ww1 * v1.x;
                h11 += ww1 * v1.y;
            }
        }
        if (e < end) {
            int rem = end - e;
            int my = 0;
            float w0 = 0.f, w1 = 0.f;
            if (lane < rem) {
                my = d_csrc[e + lane];
                float2 as = d_als2[my];
                w0 = __expf(leaky(as.x + ad.x) - m0) * inv0;
                w1 = __expf(leaky(as.y + ad.y) - m1) * inv1;
            }
            for (int t = 0; t < rem; t++) {
                int s = __shfl_sync(FULL, my, t);
                float ww0 = __shfl_sync(FULL, w0, t);
                float ww1 = __shfl_sync(FULL, w1, t);
                float2 v0 = H[s * 64 + lane];
                float2 v1 = H[s * 64 + 32 + lane];
                h00 += ww0 * v0.x;
                h01 += ww0 * v0.y;
                h10 += ww1 * v1.x;
                h11 += ww1 * v1.y;
            }
        }
        // g2 row (relu + bias): lane holds k = 2L, 2L+1, 64+2L, 65+2L
        float v00 = fmaxf(h00 + bb0.x, 0.f);
        float v01 = fmaxf(h01 + bb0.y, 0.f);
        float v10 = fmaxf(h10 + bb1.x, 0.f);
        float v11 = fmaxf(h11 + bb1.y, 0.f);

        // GEMM3: h3 = g2 @ W3  (128 -> 64)
        float a0 = 0.f, a1 = 0.f;
#pragma unroll
        for (int kk = 0; kk < 32; kk++) {
            float xb0 = __shfl_sync(FULL, v00, kk);       // k = 2kk
            float xb1 = __shfl_sync(FULL, v01, kk);       // k = 2kk+1
            float xb2 = __shfl_sync(FULL, v10, kk);       // k = 64+2kk
            float xb3 = __shfl_sync(FULL, v11, kk);       // k = 65+2kk
            float2 wA = Wp[(2 * kk) * 32 + lane];
            float2 wB = Wp[(2 * kk + 1) * 32 + lane];
            float2 wC = Wp[(64 + 2 * kk) * 32 + lane];
            float2 wD = Wp[(65 + 2 * kk) * 32 + lane];
            a0 += xb0 * wA.x + xb1 * wB.x + xb2 * wC.x + xb3 * wD.x;
            a1 += xb0 * wA.y + xb1 * wB.y + xb2 * wC.y + xb3 * wD.y;
        }
        ((float2*)d_h3)[node * 32 + lane] = make_float2(a0, a1);
        float ps = a0 * as3.x + a1 * as3.y;
        float pd = a0 * ad3.x + a1 * ad3.y;
#pragma unroll
        for (int off = 16; off; off >>= 1) {
            ps += __shfl_xor_sync(FULL, ps, off);
            pd += __shfl_xor_sync(FULL, pd, off);
        }
        if (lane == 0) {
            d_als3[node] = ps;
            d_ald3[node] = pd;
        }
    }
}

// ---------------- GAT3 aggregation (1 head, no relu) ----------------
__global__ void __launch_bounds__(256) gat3_agg_kernel(const float* __restrict__ b3, int n) {
    int warp = threadIdx.x >> 5, lane = threadIdx.x & 31;
    int node = blockIdx.x * 8 + warp;
    if (node >= n) return;
    int beg = d_rowptr[node], end = d_rowptr[node + 1];
    float ad = d_ald3[node];
    float m = -1e30f, ssum = 0.f;
    for (int e = beg + lane; e < end; e += 32) {
        int s = d_csrc[e];
        float ev = leaky(d_als3[s] + ad);
        if (ev > m) { ssum = ssum * __expf(m - ev) + 1.f; m = ev; } else ssum += __expf(ev - m);
    }
#pragma unroll
    for (int off = 16; off; off >>= 1) {
        float om = __shfl_xor_sync(FULL, m, off);
        float os = __shfl_xor_sync(FULL, ssum, off);
        float nm = fmaxf(m, om);
        ssum = ssum * __expf(m - nm) + os * __expf(om - nm);
        m = nm;
    }
    float inv = 1.f / ssum;
    float a0 = 0.f, a1 = 0.f;
    const float2* H = (const float2*)d_h3;
    int e = beg;
    for (; e + 32 <= end; e += 32) {
        int my = d_csrc[e + lane];
        float w = __expf(leaky(d_als3[my] + ad) - m) * inv;
#pragma unroll
        for (int t = 0; t < 32; t++) {
            int s = __shfl_sync(FULL, my, t);
            float ww = __shfl_sync(FULL, w, t);
            float2 v = H[s * 32 + lane];
            a0 += ww * v.x;
            a1 += ww * v.y;
        }
    }
    if (e < end) {
        int rem = end - e;
        int my = 0;
        float w = 0.f;
        if (lane < rem) {
            my = d_csrc[e + lane];
            w = __expf(leaky(d_als3[my] + ad) - m) * inv;
        }
        for (int t = 0; t < rem; t++) {
            int s = __shfl_sync(FULL, my, t);
            float ww = __shfl_sync(FULL, w, t);
            float2 v = H[s * 32 + lane];
            a0 += ww * v.x;
            a1 += ww * v.y;
        }
    }
    float2 bb = ((const float2*)b3)[lane];
    ((float2*)d_g3)[node * 32 + lane] = make_float2(a0 + bb.x, a1 + bb.y);
}

// ---------------- graph boundaries ----------------
__global__ void bounds_kernel(const void* batch, int n) {
    int is64 = g_is64;
    int i = blockIdx.x * blockDim.x + threadIdx.x;
    if (i >= n) return;
    int b = ld_idx(batch, i, is64);
    int pb = (i > 0) ? ld_idx(batch, i - 1, is64) : -1;
    for (int g = pb + 1; g <= b; ++g) d_start[g] = i;
}

// ---------------- mean-pool + fc + log_softmax ----------------
__global__ void pool_kernel(const float* __restrict__ Wfc, const float* __restrict__ bfc,
                            float* __restrict__ out) {
    int warp = threadIdx.x >> 5, lane = threadIdx.x & 31;
    int g = blockIdx.x * 8 + warp;
    if (g >= GG) return;
    int s0 = d_start[g], s1 = d_start[g + 1];
    float a0 = 0.f, a1 = 0.f;
    const float2* H = (const float2*)d_g3;
    for (int i = s0; i < s1; ++i) {
        float2 v = H[i * 32 + lane];
        a0 += v.x;
        a1 += v.y;
    }
    float inv = 1.f / fmaxf((float)(s1 - s0), 1.f);
    a0 *= inv;
    a1 *= inv;
    int c = 2 * lane;
    float l0 = a0 * Wfc[c * 2] + a1 * Wfc[(c + 1) * 2];
    float l1 = a0 * Wfc[c * 2 + 1] + a1 * Wfc[(c + 1) * 2 + 1];
#pragma unroll
    for (int off = 16; off; off >>= 1) {
        l0 += __shfl_xor_sync(FULL, l0, off);
        l1 += __shfl_xor_sync(FULL, l1, off);
    }
    if (lane == 0) {
        l0 += bfc[0];
        l1 += bfc[1];
        float mx = fmaxf(l0, l1);
        float lse = mx + logf(__expf(l0 - mx) + __expf(l1 - mx));
        out[g * 2] = l0 - lse;
        out[g * 2 + 1] = l1 - lse;
    }
}

// ---------------- host ----------------
extern "C" void kernel_launch(void* const* d_in, const int* in_sizes, int n_in,
                              void* d_out, int out_size) {
    const float* x    = (const float*)d_in[0];
    const void*  ei   = d_in[1];
    const void*  bat  = d_in[2];
    const float* W1   = (const float*)d_in[3];
    const float* b1   = (const float*)d_in[4];
    const float* W2   = (const float*)d_in[5];
    const float* as2  = (const float*)d_in[6];
    const float* ad2  = (const float*)d_in[7];
    const float* b2   = (const float*)d_in[8];
    const float* W3   = (const float*)d_in[9];
    const float* as3  = (const float*)d_in[10];
    const float* ad3  = (const float*)d_in[11];
    const float* b3   = (const float*)d_in[12];
    const float* Wfc  = (const float*)d_in[13];
    const float* bfc  = (const float*)d_in[14];
    float* out = (float*)d_out;

    const int n = in_sizes[0] / 128;   // 50000
    const int E = in_sizes[1] / 2;     // 800000
    const int nb = (n + SCAN_B - 1) / SCAN_B;

    const int PERSIST = 592;           // 4 blocks/SM

    detect_kernel<<<1, 1>>>(ei);
    init_kernel<<<(n + 256) / 256 + 1, 256>>>(n);
    count_kernel<<<(E + 255) / 256, 256>>>(ei, E);
    scanA_kernel<<<nb, SCAN_B>>>(n);
    scanB_kernel<<<1, 128>>>(nb, n);
    scanC_kernel<<<nb, SCAN_B>>>(n);
    scatter_kernel<<<(E + n + 255) / 256, 256>>>(ei, E, n);

    gemm1_kernel<<<PERSIST, 256>>>(x, W1, n);
    fused_gcn_gemm2_kernel<<<PERSIST, 256>>>(W2, b1, as2, ad2, n);
    fused_gat2_gemm3_kernel<<<PERSIST, 256>>>(W3, b2, as3, ad3, n);
    gat3_agg_kernel<<<(n + 7) / 8, 256>>>(b3, n);

    bounds_kernel<<<(n + 255) / 256, 256>>>(bat, n);
    pool_kernel<<<GG / 8, 256>>>(Wfc, bfc, out);
    (void)n_in; (void)out_size;
}